// round 10
// baseline (speedup 1.0000x reference)
#include <cuda_runtime.h>

// Atomic partial-output accumulators, one 128B L2 line per output so the 6
// counters serialize independently at the LTS. Zero at module load; the last
// block of each launch resets them, so every graph replay starts identically.
__device__ float g_acc[6 * 32];
// Last-block-done ticket, self-resetting.
__device__ int g_ticket = 0;

#define RPB 2                       // w3 rows per block
#define NBLK (256 / RPB)            // 128 blocks = one wave

__device__ __forceinline__ float dot4(float4 a, float4 b) {
    return a.x * b.x + a.y * b.y + a.z * b.z + a.w * b.w;
}

// Compute 8 consecutive conv-branch h values entirely in registers.
// q0 = first flat conv index (channel-major: q = c*D + t), D in {5,3}.
// All loads are front-batched (indices computable at entry).
template <int D>
__device__ __forceinline__ void conv8(const float* __restrict__ conv_w,
                                      const float* __restrict__ conv_b,
                                      const float* __restrict__ x, int xbase,
                                      int q0, float* h8) {
    float4 cw[8]; float cb[8]; float xv[8][4];
    #pragma unroll
    for (int k = 0; k < 8; k++) {
        const int q = q0 + k;
        const int c = q / D;
        const int t = q - c * D;
        cw[k] = *reinterpret_cast<const float4*>(conv_w + 4 * c);
        cb[k] = conv_b[c];
        #pragma unroll
        for (int m = 0; m < 4; m++) xv[k][m] = x[xbase + t + m];
    }
    #pragma unroll
    for (int k = 0; k < 8; k++) {
        float s = fmaf(cw[k].x, xv[k][0],
                  fmaf(cw[k].y, xv[k][1],
                  fmaf(cw[k].z, xv[k][2],
                  fmaf(cw[k].w, xv[k][3], cb[k]))));
        h8[k] = fmaxf(s, 0.0f);
    }
}

__global__ void __launch_bounds__(256, 1)
actor_fused_kernel(const float* __restrict__ x,
                   const float* __restrict__ conv_w, const float* __restrict__ conv_b,
                   const float* __restrict__ w0, const float* __restrict__ b0,
                   const float* __restrict__ w1, const float* __restrict__ b1,
                   const float* __restrict__ w2, const float* __restrict__ b2,
                   const float* __restrict__ w3, const float* __restrict__ b3,
                   const float* __restrict__ w4, const float* __restrict__ b4,
                   float* __restrict__ out) {
    __shared__ float red[RPB][8];

    const int tid  = threadIdx.x;
    const int lane = tid & 31;
    const int row0 = blockIdx.x * RPB;
    const int i0   = tid * 8;          // this thread's h slice [i0, i0+8)

    // ---- w3 slices for this block's 2 rows (4x LDG.128, coalesced) ----
    const float4* wr0 = reinterpret_cast<const float4*>(w3 + (size_t)row0 * 2048);
    const float4* wr1 = reinterpret_cast<const float4*>(w3 + (size_t)(row0 + 1) * 2048);
    const float4 a0 = wr0[tid * 2], a1 = wr0[tid * 2 + 1];
    const float4 c0 = wr1[tid * 2], c1 = wr1[tid * 2 + 1];

    // ---- tail params (threads 0..5 fold both rows into one RED) ----
    const float b3r0 = b3[row0];
    const float b3r1 = b3[row0 + 1];
    const int   o6   = (tid < 6) ? tid : 0;
    const float w4a  = w4[o6 * 256 + row0];        // w4[o][row0]
    const float w4b  = w4[o6 * 256 + row0 + 1];    // w4[o][row0+1]
    const float b4p  = b4[lane < 6 ? lane : 0];

    // ---- This thread's 8 h values, entirely in registers. Segment
    //      boundaries (128,256,896,1536,1920) are multiples of 8, so each
    //      thread's slice lies in exactly one branch. Layout:
    // h[   0: 128) = relu(w0*x[0,7] + b0)
    // h[ 128: 256) = relu(w1*x[1,7] + b1)
    // h[ 256: 896) = relu(conv1d(x[2,0:8]))  channel-major [128,5]
    // h[ 896:1536) = relu(conv1d(x[3,0:8]))  channel-major [128,5]
    // h[1536:1920) = relu(conv1d(x[4,0:6]))  channel-major [128,3]
    // h[1920:2048) = w2*x[4,7] + b2          (NO relu)
    float h8[8];
    if (tid < 16) {
        const float xs = x[7];
        const float4 wA = *reinterpret_cast<const float4*>(w0 + i0);
        const float4 wB = *reinterpret_cast<const float4*>(w0 + i0 + 4);
        const float4 bA = *reinterpret_cast<const float4*>(b0 + i0);
        const float4 bB = *reinterpret_cast<const float4*>(b0 + i0 + 4);
        h8[0] = fmaxf(fmaf(wA.x, xs, bA.x), 0.0f);
        h8[1] = fmaxf(fmaf(wA.y, xs, bA.y), 0.0f);
        h8[2] = fmaxf(fmaf(wA.z, xs, bA.z), 0.0f);
        h8[3] = fmaxf(fmaf(wA.w, xs, bA.w), 0.0f);
        h8[4] = fmaxf(fmaf(wB.x, xs, bB.x), 0.0f);
        h8[5] = fmaxf(fmaf(wB.y, xs, bB.y), 0.0f);
        h8[6] = fmaxf(fmaf(wB.z, xs, bB.z), 0.0f);
        h8[7] = fmaxf(fmaf(wB.w, xs, bB.w), 0.0f);
    } else if (tid < 32) {
        const float xs = x[15];
        const int off = i0 - 128;
        const float4 wA = *reinterpret_cast<const float4*>(w1 + off);
        const float4 wB = *reinterpret_cast<const float4*>(w1 + off + 4);
        const float4 bA = *reinterpret_cast<const float4*>(b1 + off);
        const float4 bB = *reinterpret_cast<const float4*>(b1 + off + 4);
        h8[0] = fmaxf(fmaf(wA.x, xs, bA.x), 0.0f);
        h8[1] = fmaxf(fmaf(wA.y, xs, bA.y), 0.0f);
        h8[2] = fmaxf(fmaf(wA.z, xs, bA.z), 0.0f);
        h8[3] = fmaxf(fmaf(wA.w, xs, bA.w), 0.0f);
        h8[4] = fmaxf(fmaf(wB.x, xs, bB.x), 0.0f);
        h8[5] = fmaxf(fmaf(wB.y, xs, bB.y), 0.0f);
        h8[6] = fmaxf(fmaf(wB.z, xs, bB.z), 0.0f);
        h8[7] = fmaxf(fmaf(wB.w, xs, bB.w), 0.0f);
    } else if (tid < 112) {
        conv8<5>(conv_w, conv_b, x, 16, i0 - 256, h8);
    } else if (tid < 192) {
        conv8<5>(conv_w, conv_b, x, 24, i0 - 896, h8);
    } else if (tid < 240) {
        conv8<3>(conv_w, conv_b, x, 32, i0 - 1536, h8);
    } else {
        const float xs = x[39];
        const int off = i0 - 1920;
        const float4 wA = *reinterpret_cast<const float4*>(w2 + off);
        const float4 wB = *reinterpret_cast<const float4*>(w2 + off + 4);
        const float4 bA = *reinterpret_cast<const float4*>(b2 + off);
        const float4 bB = *reinterpret_cast<const float4*>(b2 + off + 4);
        h8[0] = fmaf(wA.x, xs, bA.x);      // no relu
        h8[1] = fmaf(wA.y, xs, bA.y);
        h8[2] = fmaf(wA.z, xs, bA.z);
        h8[3] = fmaf(wA.w, xs, bA.w);
        h8[4] = fmaf(wB.x, xs, bB.x);
        h8[5] = fmaf(wB.y, xs, bB.y);
        h8[6] = fmaf(wB.z, xs, bB.z);
        h8[7] = fmaf(wB.w, xs, bB.w);
    }

    // ---- partial dots for this block's 2 rows (h never touches memory) ----
    const float4 H0 = make_float4(h8[0], h8[1], h8[2], h8[3]);
    const float4 H1 = make_float4(h8[4], h8[5], h8[6], h8[7]);
    float p0 = dot4(a0, H0) + dot4(a1, H1);
    float p1 = dot4(c0, H0) + dot4(c1, H1);

    // Two independent shuffle chains; scheduler overlaps them.
    #pragma unroll
    for (int o = 16; o > 0; o >>= 1) {
        p0 += __shfl_down_sync(0xFFFFFFFFu, p0, o);
        p1 += __shfl_down_sync(0xFFFFFFFFu, p1, o);
    }
    if (lane == 0) {
        red[0][tid >> 5] = p0;
        red[1][tid >> 5] = p1;
    }
    __syncthreads();                 // the ONLY block barrier

    // ---- Warp 0 only: folded partial outputs + ticket + fused tail ----
    if (tid < 32) {
        if (tid < 6) {
            // pairwise trees over 8 warp partials, both rows
            float s0 = (red[0][0] + red[0][1]) + (red[0][2] + red[0][3])
                     + ((red[0][4] + red[0][5]) + (red[0][6] + red[0][7]));
            float s1 = (red[1][0] + red[1][1]) + (red[1][2] + red[1][3])
                     + ((red[1][4] + red[1][5]) + (red[1][6] + red[1][7]));
            const float h2a = fmaxf(s0 + b3r0, 0.0f);
            const float h2b = fmaxf(s1 + b3r1, 0.0f);
            // one RED per output per block (128 per address network-wide)
            atomicAdd(&g_acc[tid * 32], fmaf(h2a, w4a, h2b * w4b));
        }
        __syncwarp();                          // REDs happen-before tid0's fence
        int t = 0;
        if (lane == 0) {
            __threadfence();                   // release warp-0 REDs device-wide
            t = atomicAdd(&g_ticket, 1);
        }
        t = __shfl_sync(0xFFFFFFFFu, t, 0);
        if (t == NBLK - 1) {
            __threadfence();                   // acquire: all blocks' REDs visible
            if (lane < 6) {
                float acc = __ldcg(&g_acc[lane * 32]);
                out[lane] = acc + b4p;
                g_acc[lane * 32] = 0.0f;       // reset for next replay
            }
            if (lane == 0) g_ticket = 0;
        }
    }
}

extern "C" void kernel_launch(void* const* d_in, const int* in_sizes, int n_in,
                              void* d_out, int out_size) {
    const float* x      = (const float*)d_in[0];
    const float* conv_w = (const float*)d_in[1];
    const float* conv_b = (const float*)d_in[2];
    const float* w0 = (const float*)d_in[3];
    const float* b0 = (const float*)d_in[4];
    const float* w1 = (const float*)d_in[5];
    const float* b1 = (const float*)d_in[6];
    const float* w2 = (const float*)d_in[7];
    const float* b2 = (const float*)d_in[8];
    const float* w3 = (const float*)d_in[9];
    const float* b3 = (const float*)d_in[10];
    const float* w4 = (const float*)d_in[11];
    const float* b4 = (const float*)d_in[12];
    float* out = (float*)d_out;

    actor_fused_kernel<<<NBLK, 256>>>(x, conv_w, conv_b,
                                      w0, b0, w1, b1, w2, b2, w3, b3,
                                      w4, b4, out);
}